// round 2
// baseline (speedup 1.0000x reference)
#include <cuda_runtime.h>
#include <cuda_bf16.h>
#include <math.h>

// Problem constants (dataset-fixed)
#define MAXN 100000
#define MAXE 1600000
#define FIN  512
#define HID  64
#define NCLS 16

// ---------------- device scratch (no allocation allowed) ----------------
__device__ float g_support1[MAXN * HID];     // x @ W1
__device__ float g_h[MAXN * HID];            // relu(A @ support1 + b1)
__device__ float g_support2[MAXN * NCLS];    // h @ W2
__device__ int   g_cnt[MAXN];
__device__ int   g_incl[MAXN];
__device__ int   g_rowoff[MAXN + 1];
__device__ int   g_blockSums[512];
__device__ int   g_blockOff[512];
__device__ int   g_csr_src[MAXE];
__device__ float g_csr_val[MAXE];

// ---------------- small utilities ----------------
__device__ __forceinline__ int warp_incl_scan(int v) {
    int lane = threadIdx.x & 31;
#pragma unroll
    for (int d = 1; d < 32; d <<= 1) {
        int t = __shfl_up_sync(0xffffffffu, v, d);
        if (lane >= d) v += t;
    }
    return v;
}

__global__ void zero_cnt_kernel(int n) {
    int i = blockIdx.x * 256 + threadIdx.x;
    if (i < n) g_cnt[i] = 0;
}

__global__ void hist_kernel(const int* __restrict__ dst, int e) {
    int i = blockIdx.x * 256 + threadIdx.x;
    if (i < e) atomicAdd(&g_cnt[dst[i]], 1);
}

// per-512-block inclusive scan of g_cnt -> g_incl, block totals -> g_blockSums
__global__ void scan1_kernel(int n) {
    __shared__ int warpS[16];
    int tid = threadIdx.x;
    int gid = blockIdx.x * 512 + tid;
    int v = (gid < n) ? g_cnt[gid] : 0;
    int s = warp_incl_scan(v);
    int wid = tid >> 5, lane = tid & 31;
    if (lane == 31) warpS[wid] = s;
    __syncthreads();
    if (wid == 0) {
        int wv = (lane < 16) ? warpS[lane] : 0;
        int ws = warp_incl_scan(wv);
        if (lane < 16) warpS[lane] = ws;
    }
    __syncthreads();
    int off = (wid > 0) ? warpS[wid - 1] : 0;
    s += off;
    if (gid < n) g_incl[gid] = s;
    if (tid == 511) g_blockSums[blockIdx.x] = s;
}

// exclusive scan of block sums (nb <= 256) -> g_blockOff
__global__ void scan2_kernel(int nb) {
    __shared__ int warpS[8];
    int tid = threadIdx.x;
    int v = (tid < nb) ? g_blockSums[tid] : 0;
    int s = warp_incl_scan(v);
    int wid = tid >> 5, lane = tid & 31;
    if (lane == 31) warpS[wid] = s;
    __syncthreads();
    if (wid == 0) {
        int wv = (lane < 8) ? warpS[lane] : 0;
        int ws = warp_incl_scan(wv);
        if (lane < 8) warpS[lane] = ws;
    }
    __syncthreads();
    int off = (wid > 0) ? warpS[wid - 1] : 0;
    if (tid < nb) g_blockOff[tid] = s + off - v;  // exclusive
}

// row offsets: rowoff[0]=0 ; rowoff[i+1] = incl[i] + blockOff[i/512]
// Also resets g_cnt so the scatter pass can reuse it (fuses a launch).
__global__ void scan3_kernel(int n) {
    int gid = blockIdx.x * 256 + threadIdx.x;
    if (gid == 0) g_rowoff[0] = 0;
    if (gid < n) {
        g_rowoff[gid + 1] = g_incl[gid] + g_blockOff[gid >> 9];
        g_cnt[gid] = 0;
    }
}

__global__ void scatter_kernel(const int* __restrict__ src,
                               const int* __restrict__ dst,
                               const float* __restrict__ val, int e) {
    int i = blockIdx.x * 256 + threadIdx.x;
    if (i < e) {
        int d = dst[i];
        int p = g_rowoff[d] + atomicAdd(&g_cnt[d], 1);
        g_csr_src[p] = src[i];
        g_csr_val[p] = val[i];
    }
}

// ---------------- GEMM1: support1 = x[N,512] @ W1[512,64] ----------------
// 128 threads, block tile 128x64, BK=16, per-thread 8x8 register tile held
// as f32x2 pairs so the inner product runs on FFMA2 (packed fp32, 2x rate).
#define BM 128
#define BN 64
#define BK 16

__global__ __launch_bounds__(128) void gemm1_kernel(const float* __restrict__ x,
                                                    const float* __restrict__ W1,
                                                    int N) {
    __shared__ float As[BK][BM + 4];   // transposed x tile, stride 132 floats
    __shared__ float Bs[BK][BN + 4];   // stride 68 floats (16B-aligned rows)
    int tid = threadIdx.x;
    int tx = tid & 7;          // col group -> cols tx*8 .. tx*8+7
    int ty = tid >> 3;         // row group -> rows ty*8 .. ty*8+7
    int block_row = blockIdx.x * BM;

    unsigned long long acc[8][4];
#pragma unroll
    for (int i = 0; i < 8; i++)
#pragma unroll
        for (int j = 0; j < 4; j++) acc[i][j] = 0ull;

    int af4 = tid & 3;         // which float4 of the 16-wide k-chunk
    int ar  = tid >> 2;        // 0..31  row within 32-row group
    int bf4 = tid & 15;        // which float4 of the 64-wide row
    int bk  = tid >> 4;        // 0..7

    for (int k0 = 0; k0 < FIN; k0 += BK) {
        // load A tile (transposed into As[k][row])
#pragma unroll
        for (int i = 0; i < 4; i++) {
            int r = ar + 32 * i;
            int gr = block_row + r;
            float4 v = make_float4(0.f, 0.f, 0.f, 0.f);
            if (gr < N) v = *(const float4*)(x + (size_t)gr * FIN + k0 + af4 * 4);
            As[af4 * 4 + 0][r] = v.x; As[af4 * 4 + 1][r] = v.y;
            As[af4 * 4 + 2][r] = v.z; As[af4 * 4 + 3][r] = v.w;
        }
        // load B tile
#pragma unroll
        for (int i = 0; i < 2; i++) {
            int kr = bk + 8 * i;
            float4 v = *(const float4*)(W1 + (size_t)(k0 + kr) * HID + bf4 * 4);
            *(float4*)&Bs[kr][bf4 * 4] = v;
        }
        __syncthreads();

#pragma unroll
        for (int k = 0; k < BK; k++) {
            float a[8];
            *(float4*)&a[0] = *(const float4*)&As[k][ty * 8];
            *(float4*)&a[4] = *(const float4*)&As[k][ty * 8 + 4];
            unsigned long long b[4];
            {
                ulonglong2 b01 = *(const ulonglong2*)&Bs[k][tx * 8];
                ulonglong2 b23 = *(const ulonglong2*)&Bs[k][tx * 8 + 4];
                b[0] = b01.x; b[1] = b01.y; b[2] = b23.x; b[3] = b23.y;
            }
#pragma unroll
            for (int i = 0; i < 8; i++) {
                unsigned long long ad;
                asm("mov.b64 %0, {%1, %1};" : "=l"(ad) : "r"(__float_as_uint(a[i])));
#pragma unroll
                for (int j = 0; j < 4; j++) {
                    asm("fma.rn.f32x2 %0, %1, %2, %0;"
                        : "+l"(acc[i][j]) : "l"(ad), "l"(b[j]));
                }
            }
        }
        __syncthreads();
    }

    // epilogue
#pragma unroll
    for (int i = 0; i < 8; i++) {
        int gr = block_row + ty * 8 + i;
        if (gr < N) {
            float o[8];
#pragma unroll
            for (int j = 0; j < 4; j++) {
                unsigned lo, hi;
                asm("mov.b64 {%0, %1}, %2;" : "=r"(lo), "=r"(hi) : "l"(acc[i][j]));
                o[j * 2]     = __uint_as_float(lo);
                o[j * 2 + 1] = __uint_as_float(hi);
            }
            *(float4*)&g_support1[(size_t)gr * HID + tx * 8]     = *(float4*)&o[0];
            *(float4*)&g_support1[(size_t)gr * HID + tx * 8 + 4] = *(float4*)&o[4];
        }
    }
}

// ---------------- SpMM1: h = relu(A @ support1 + b1) ----------------
// Warp per node; half-warp per edge, float4 per lane (1 LDG.128 covers 2 edges).
__global__ __launch_bounds__(256) void spmm1_kernel(const float* __restrict__ b1, int N) {
    int warp = (blockIdx.x * blockDim.x + threadIdx.x) >> 5;
    int lane = threadIdx.x & 31;
    if (warp >= N) return;
    int s = g_rowoff[warp];
    int e = g_rowoff[warp + 1];
    int half = lane >> 4;        // 0 or 1: which edge of the pair
    int c4 = (lane & 15) * 4;    // column offset within the 64-wide row
    float4 acc = make_float4(0.f, 0.f, 0.f, 0.f);
    for (int i = s; i + half < e; i += 2) {
        int idx = i + half;
        int src = g_csr_src[idx];
        float v = g_csr_val[idx];
        float4 r = *(const float4*)&g_support1[(size_t)src * HID + c4];
        acc.x += v * r.x; acc.y += v * r.y; acc.z += v * r.z; acc.w += v * r.w;
    }
    acc.x += __shfl_down_sync(0xffffffffu, acc.x, 16);
    acc.y += __shfl_down_sync(0xffffffffu, acc.y, 16);
    acc.z += __shfl_down_sync(0xffffffffu, acc.z, 16);
    acc.w += __shfl_down_sync(0xffffffffu, acc.w, 16);
    if (lane < 16) {
        float4 bb = *(const float4*)&b1[c4];
        float4 o;
        o.x = fmaxf(acc.x + bb.x, 0.f);
        o.y = fmaxf(acc.y + bb.y, 0.f);
        o.z = fmaxf(acc.z + bb.z, 0.f);
        o.w = fmaxf(acc.w + bb.w, 0.f);
        *(float4*)&g_h[(size_t)warp * HID + c4] = o;
    }
}

// ---------------- GEMM2: support2 = h[N,64] @ W2[64,16] ----------------
__global__ __launch_bounds__(256) void gemm2_kernel(const float* __restrict__ W2, int N) {
    __shared__ float Ws[HID * NCLS];
    int tid = threadIdx.x;
    for (int i = tid; i < HID * NCLS; i += 256) Ws[i] = W2[i];
    __syncthreads();
    int lane = tid & 31, wid = tid >> 5;
    int row = (blockIdx.x * 8 + wid) * 2 + (lane >> 4);
    int col = lane & 15;
    if (row >= N) return;
    const float* hr = &g_h[(size_t)row * HID];
    float acc = 0.f;
#pragma unroll
    for (int k = 0; k < HID; k++) acc += hr[k] * Ws[k * NCLS + col];
    g_support2[(size_t)row * NCLS + col] = acc;
}

// ------- SpMM2 + b2 + softmax: out = softmax(A @ support2 + b2) ---------
__global__ __launch_bounds__(256) void spmm2_softmax_kernel(const float* __restrict__ b2,
                                                            float* __restrict__ out, int N) {
    int warp = (blockIdx.x * blockDim.x + threadIdx.x) >> 5;
    int lane = threadIdx.x & 31;
    if (warp >= N) return;
    int s = g_rowoff[warp];
    int e = g_rowoff[warp + 1];
    int col = lane & 15;
    float acc = 0.f;
    for (int i = s; i < e; i += 2) {
        int idx = i + (lane >> 4);
        if (idx < e) {
            int src = g_csr_src[idx];
            float v = g_csr_val[idx];
            acc += v * g_support2[(size_t)src * NCLS + col];
        }
    }
    acc += __shfl_down_sync(0xffffffffu, acc, 16);
    float logit = acc + b2[col];
    float m = logit;
#pragma unroll
    for (int d = 8; d >= 1; d >>= 1) m = fmaxf(m, __shfl_xor_sync(0xffffffffu, m, d));
    float ev = __expf(logit - m);
    float sum = ev;
#pragma unroll
    for (int d = 8; d >= 1; d >>= 1) sum += __shfl_xor_sync(0xffffffffu, sum, d);
    if (lane < 16) out[(size_t)warp * NCLS + col] = ev / sum;
}

// ---------------- launch ----------------
extern "C" void kernel_launch(void* const* d_in, const int* in_sizes, int n_in,
                              void* d_out, int out_size) {
    const float* x        = (const float*)d_in[0];
    const int*   edge_src = (const int*)d_in[1];
    const int*   edge_dst = (const int*)d_in[2];
    const float* edge_val = (const float*)d_in[3];
    const float* W1       = (const float*)d_in[4];
    const float* b1       = (const float*)d_in[5];
    const float* W2       = (const float*)d_in[6];
    const float* b2       = (const float*)d_in[7];
    float* out = (float*)d_out;

    int E = in_sizes[1];
    int N = in_sizes[0] / FIN;

    int nblkN = (N + 255) / 256;
    int nblkE = (E + 255) / 256;
    int nbScan = (N + 511) / 512;

    // CSR build (by dst) — gemm1 is placed as the 6th launch so the ncu
    // window (-s 5 -c 1) profiles the dominant kernel.
    zero_cnt_kernel<<<nblkN, 256>>>(N);                          // 1
    hist_kernel<<<nblkE, 256>>>(edge_dst, E);                    // 2
    scan1_kernel<<<nbScan, 512>>>(N);                            // 3
    scan2_kernel<<<1, 256>>>(nbScan);                            // 4
    scan3_kernel<<<nblkN, 256>>>(N);                             // 5 (also resets cnt)
    gemm1_kernel<<<(N + BM - 1) / BM, 128>>>(x, W1, N);          // 6  <- profiled
    scatter_kernel<<<nblkE, 256>>>(edge_src, edge_dst, edge_val, E); // 7
    spmm1_kernel<<<(N + 7) / 8, 256>>>(b1, N);                   // 8
    gemm2_kernel<<<(N + 15) / 16, 256>>>(W2, N);                 // 9
    spmm2_softmax_kernel<<<(N + 7) / 8, 256>>>(b2, out, N);      // 10
}

// round 16
// speedup vs baseline: 2.0439x; 2.0439x over previous
#include <cuda_runtime.h>
#include <cuda_bf16.h>
#include <math.h>
#include <stdint.h>

// Problem constants (dataset-fixed)
#define MAXN 100000
#define MAXE 1600000
#define FIN  512
#define HID  64
#define NCLS 16

// ---------------- device scratch (no allocation allowed) ----------------
__device__ float g_support1[MAXN * HID];     // x @ W1
__device__ float g_h[MAXN * HID];            // relu(A @ support1 + b1)
__device__ float g_support2[MAXN * NCLS];    // h @ W2
__device__ int   g_cnt[MAXN];
__device__ int   g_incl[MAXN];
__device__ int   g_rowoff[MAXN + 1];
__device__ int   g_blockSums[512];
__device__ int   g_blockOff[512];
__device__ int   g_csr_src[MAXE];
__device__ float g_csr_val[MAXE];

// ---------------- small utilities ----------------
__device__ __forceinline__ int warp_incl_scan(int v) {
    int lane = threadIdx.x & 31;
#pragma unroll
    for (int d = 1; d < 32; d <<= 1) {
        int t = __shfl_up_sync(0xffffffffu, v, d);
        if (lane >= d) v += t;
    }
    return v;
}

__device__ __forceinline__ uint32_t smem_u32(const void* p) {
    return (uint32_t)__cvta_generic_to_shared(p);
}

__device__ __forceinline__ void ldsm_x4(uint32_t* d, uint32_t addr) {
    asm volatile("ldmatrix.sync.aligned.m8n8.x4.shared.b16 {%0,%1,%2,%3}, [%4];"
                 : "=r"(d[0]), "=r"(d[1]), "=r"(d[2]), "=r"(d[3]) : "r"(addr));
}
__device__ __forceinline__ void ldsm_x4_t(uint32_t* d, uint32_t addr) {
    asm volatile("ldmatrix.sync.aligned.m8n8.x4.trans.shared.b16 {%0,%1,%2,%3}, [%4];"
                 : "=r"(d[0]), "=r"(d[1]), "=r"(d[2]), "=r"(d[3]) : "r"(addr));
}
__device__ __forceinline__ void mma16816(float* c, const uint32_t* a, uint32_t b0, uint32_t b1) {
    asm volatile("mma.sync.aligned.m16n8k16.row.col.f32.bf16.bf16.f32 "
                 "{%0,%1,%2,%3}, {%4,%5,%6,%7}, {%8,%9}, {%0,%1,%2,%3};"
                 : "+f"(c[0]), "+f"(c[1]), "+f"(c[2]), "+f"(c[3])
                 : "r"(a[0]), "r"(a[1]), "r"(a[2]), "r"(a[3]), "r"(b0), "r"(b1));
}

__global__ void zero_cnt_kernel(int n) {
    int i = blockIdx.x * 256 + threadIdx.x;
    if (i < n) g_cnt[i] = 0;
}

__global__ void hist_kernel(const int* __restrict__ dst, int e) {
    int i = blockIdx.x * 256 + threadIdx.x;
    if (i < e) atomicAdd(&g_cnt[dst[i]], 1);
}

// per-512-block inclusive scan of g_cnt -> g_incl, block totals -> g_blockSums
__global__ void scan1_kernel(int n) {
    __shared__ int warpS[16];
    int tid = threadIdx.x;
    int gid = blockIdx.x * 512 + tid;
    int v = (gid < n) ? g_cnt[gid] : 0;
    int s = warp_incl_scan(v);
    int wid = tid >> 5, lane = tid & 31;
    if (lane == 31) warpS[wid] = s;
    __syncthreads();
    if (wid == 0) {
        int wv = (lane < 16) ? warpS[lane] : 0;
        int ws = warp_incl_scan(wv);
        if (lane < 16) warpS[lane] = ws;
    }
    __syncthreads();
    int off = (wid > 0) ? warpS[wid - 1] : 0;
    s += off;
    if (gid < n) g_incl[gid] = s;
    if (tid == 511) g_blockSums[blockIdx.x] = s;
}

// exclusive scan of block sums (nb <= 256) -> g_blockOff
__global__ void scan2_kernel(int nb) {
    __shared__ int warpS[8];
    int tid = threadIdx.x;
    int v = (tid < nb) ? g_blockSums[tid] : 0;
    int s = warp_incl_scan(v);
    int wid = tid >> 5, lane = tid & 31;
    if (lane == 31) warpS[wid] = s;
    __syncthreads();
    if (wid == 0) {
        int wv = (lane < 8) ? warpS[lane] : 0;
        int ws = warp_incl_scan(wv);
        if (lane < 8) warpS[lane] = ws;
    }
    __syncthreads();
    int off = (wid > 0) ? warpS[wid - 1] : 0;
    if (tid < nb) g_blockOff[tid] = s + off - v;  // exclusive
}

// row offsets: rowoff[0]=0 ; rowoff[i+1] = incl[i] + blockOff[i/512]
// Also resets g_cnt so the scatter pass can reuse it.
__global__ void scan3_kernel(int n) {
    int gid = blockIdx.x * 256 + threadIdx.x;
    if (gid == 0) g_rowoff[0] = 0;
    if (gid < n) {
        g_rowoff[gid + 1] = g_incl[gid] + g_blockOff[gid >> 9];
        g_cnt[gid] = 0;
    }
}

__global__ void scatter_kernel(const int* __restrict__ src,
                               const int* __restrict__ dst,
                               const float* __restrict__ val, int e) {
    int i = blockIdx.x * 256 + threadIdx.x;
    if (i < e) {
        int d = dst[i];
        int p = g_rowoff[d] + atomicAdd(&g_cnt[d], 1);
        g_csr_src[p] = src[i];
        g_csr_val[p] = val[i];
    }
}

// ---------------- GEMM1 (tensor cores): support1 = x[N,512] @ W1[512,64] ---
// bf16 hi/lo split, 3 HMMA products (hi*hi + hi*lo + lo*hi) accumulated in
// fp32 -> ~1e-5 relative error. Block tile 128x64, K-chunk 32, 8 warps,
// warp tile 16x64 via mma.m16n8k16.
#define APITCH 40   // bf16 elems per A smem row (80B: conflict-free ldmatrix)
#define BPITCH 72   // bf16 elems per B smem row (144B: conflict-free ldmatrix)

__global__ __launch_bounds__(256) void gemm1_mma_kernel(const float* __restrict__ x,
                                                        const float* __restrict__ W1,
                                                        int N) {
    __shared__ __align__(16) __nv_bfloat16 Ahi[128 * APITCH];
    __shared__ __align__(16) __nv_bfloat16 Alo[128 * APITCH];
    __shared__ __align__(16) __nv_bfloat16 Bhi[32 * BPITCH];
    __shared__ __align__(16) __nv_bfloat16 Blo[32 * BPITCH];

    int tid = threadIdx.x, lane = tid & 31, warp = tid >> 5;
    int block_row = blockIdx.x * 128;

    float acc[8][4];
#pragma unroll
    for (int i = 0; i < 8; i++)
#pragma unroll
        for (int j = 0; j < 4; j++) acc[i][j] = 0.f;

    int a_f4 = tid & 7;   // float4 index within 32-wide k-chunk
    int a_r  = tid >> 3;  // 0..31 (rows r, r+32, r+64, r+96)
    int b_f4 = tid & 15;  // float4 index within 64-wide row
    int b_r  = tid >> 4;  // 0..15 (k-rows r, r+16)

    int m0 = warp * 16;
    // ldmatrix base addresses (within-chunk k offset added in the loop)
    uint32_t aHiAddr = smem_u32(&Ahi[(m0 + (lane & 15)) * APITCH + (lane >> 4) * 8]);
    uint32_t aLoAddr = smem_u32(&Alo[(m0 + (lane & 15)) * APITCH + (lane >> 4) * 8]);
    uint32_t bHiAddr = smem_u32(&Bhi[(lane & 15) * BPITCH + (lane >> 4) * 8]);
    uint32_t bLoAddr = smem_u32(&Blo[(lane & 15) * BPITCH + (lane >> 4) * 8]);

    for (int k0 = 0; k0 < FIN; k0 += 32) {
        // ---- load + split A tile (128 rows x 32 k) ----
#pragma unroll
        for (int i = 0; i < 4; i++) {
            int r = a_r + 32 * i;
            int gr = block_row + r;
            float4 v = make_float4(0.f, 0.f, 0.f, 0.f);
            if (gr < N) v = *(const float4*)(x + (size_t)gr * FIN + k0 + a_f4 * 4);
            float vv[4] = {v.x, v.y, v.z, v.w};
            __nv_bfloat16 h[4], l[4];
#pragma unroll
            for (int j = 0; j < 4; j++) {
                h[j] = __float2bfloat16(vv[j]);
                l[j] = __float2bfloat16(vv[j] - __bfloat162float(h[j]));
            }
            int base = r * APITCH + a_f4 * 4;
            *(__nv_bfloat162*)&Ahi[base]     = __nv_bfloat162(h[0], h[1]);
            *(__nv_bfloat162*)&Ahi[base + 2] = __nv_bfloat162(h[2], h[3]);
            *(__nv_bfloat162*)&Alo[base]     = __nv_bfloat162(l[0], l[1]);
            *(__nv_bfloat162*)&Alo[base + 2] = __nv_bfloat162(l[2], l[3]);
        }
        // ---- load + split B tile (32 k x 64 n) ----
#pragma unroll
        for (int i = 0; i < 2; i++) {
            int kr = b_r + 16 * i;
            float4 v = *(const float4*)(W1 + (size_t)(k0 + kr) * HID + b_f4 * 4);
            float vv[4] = {v.x, v.y, v.z, v.w};
            __nv_bfloat16 h[4], l[4];
#pragma unroll
            for (int j = 0; j < 4; j++) {
                h[j] = __float2bfloat16(vv[j]);
                l[j] = __float2bfloat16(vv[j] - __bfloat162float(h[j]));
            }
            int base = kr * BPITCH + b_f4 * 4;
            *(__nv_bfloat162*)&Bhi[base]     = __nv_bfloat162(h[0], h[1]);
            *(__nv_bfloat162*)&Bhi[base + 2] = __nv_bfloat162(h[2], h[3]);
            *(__nv_bfloat162*)&Blo[base]     = __nv_bfloat162(l[0], l[1]);
            *(__nv_bfloat162*)&Blo[base + 2] = __nv_bfloat162(l[2], l[3]);
        }
        __syncthreads();

#pragma unroll
        for (int k16 = 0; k16 < 2; k16++) {
            uint32_t ah[4], al[4];
            ldsm_x4(ah, aHiAddr + k16 * 32);          // 16 bf16 = 32B col offset
            ldsm_x4(al, aLoAddr + k16 * 32);
            uint32_t bh[4][4], bl[4][4];
#pragma unroll
            for (int p = 0; p < 4; p++) {
                uint32_t koff = (uint32_t)(k16 * 16 * BPITCH * 2);
                ldsm_x4_t(bh[p], bHiAddr + koff + p * 32);
                ldsm_x4_t(bl[p], bLoAddr + koff + p * 32);
            }
#pragma unroll
            for (int p = 0; p < 4; p++) {
#pragma unroll
                for (int hh = 0; hh < 2; hh++) {
                    int nb = p * 2 + hh;
                    mma16816(acc[nb], ah, bh[p][2 * hh], bh[p][2 * hh + 1]);
                    mma16816(acc[nb], ah, bl[p][2 * hh], bl[p][2 * hh + 1]);
                    mma16816(acc[nb], al, bh[p][2 * hh], bh[p][2 * hh + 1]);
                }
            }
        }
        __syncthreads();
    }

    // epilogue: c0,c1 -> row m0+(lane>>2), cols nb*8+(lane&3)*2; c2,c3 -> row+8
    int er = block_row + m0 + (lane >> 2);
    int ec = (lane & 3) * 2;
#pragma unroll
    for (int nb = 0; nb < 8; nb++) {
        if (er < N)
            *(float2*)&g_support1[(size_t)er * HID + nb * 8 + ec] =
                make_float2(acc[nb][0], acc[nb][1]);
        if (er + 8 < N)
            *(float2*)&g_support1[(size_t)(er + 8) * HID + nb * 8 + ec] =
                make_float2(acc[nb][2], acc[nb][3]);
    }
}

// ---------------- SpMM1: h = relu(A @ support1 + b1) ----------------
// Warp per node; half-warp per edge, float4 per lane.
__global__ __launch_bounds__(256) void spmm1_kernel(const float* __restrict__ b1, int N) {
    int warp = (blockIdx.x * blockDim.x + threadIdx.x) >> 5;
    int lane = threadIdx.x & 31;
    if (warp >= N) return;
    int s = g_rowoff[warp];
    int e = g_rowoff[warp + 1];
    int half = lane >> 4;
    int c4 = (lane & 15) * 4;
    float4 acc = make_float4(0.f, 0.f, 0.f, 0.f);
    for (int i = s; i + half < e; i += 2) {
        int idx = i + half;
        int src = g_csr_src[idx];
        float v = g_csr_val[idx];
        float4 r = *(const float4*)&g_support1[(size_t)src * HID + c4];
        acc.x += v * r.x; acc.y += v * r.y; acc.z += v * r.z; acc.w += v * r.w;
    }
    acc.x += __shfl_down_sync(0xffffffffu, acc.x, 16);
    acc.y += __shfl_down_sync(0xffffffffu, acc.y, 16);
    acc.z += __shfl_down_sync(0xffffffffu, acc.z, 16);
    acc.w += __shfl_down_sync(0xffffffffu, acc.w, 16);
    if (lane < 16) {
        float4 bb = *(const float4*)&b1[c4];
        float4 o;
        o.x = fmaxf(acc.x + bb.x, 0.f);
        o.y = fmaxf(acc.y + bb.y, 0.f);
        o.z = fmaxf(acc.z + bb.z, 0.f);
        o.w = fmaxf(acc.w + bb.w, 0.f);
        *(float4*)&g_h[(size_t)warp * HID + c4] = o;
    }
}

// ---------------- GEMM2: support2 = h[N,64] @ W2[64,16] ----------------
__global__ __launch_bounds__(256) void gemm2_kernel(const float* __restrict__ W2, int N) {
    __shared__ float Ws[HID * NCLS];
    int tid = threadIdx.x;
    for (int i = tid; i < HID * NCLS; i += 256) Ws[i] = W2[i];
    __syncthreads();
    int lane = tid & 31, wid = tid >> 5;
    int row = (blockIdx.x * 8 + wid) * 2 + (lane >> 4);
    int col = lane & 15;
    if (row >= N) return;
    const float* hr = &g_h[(size_t)row * HID];
    float acc = 0.f;
#pragma unroll
    for (int k = 0; k < HID; k++) acc += hr[k] * Ws[k * NCLS + col];
    g_support2[(size_t)row * NCLS + col] = acc;
}

// ------- SpMM2 + b2 + softmax: out = softmax(A @ support2 + b2) ---------
__global__ __launch_bounds__(256) void spmm2_softmax_kernel(const float* __restrict__ b2,
                                                            float* __restrict__ out, int N) {
    int warp = (blockIdx.x * blockDim.x + threadIdx.x) >> 5;
    int lane = threadIdx.x & 31;
    if (warp >= N) return;
    int s = g_rowoff[warp];
    int e = g_rowoff[warp + 1];
    int col = lane & 15;
    float acc = 0.f;
    for (int i = s; i < e; i += 2) {
        int idx = i + (lane >> 4);
        if (idx < e) {
            int src = g_csr_src[idx];
            float v = g_csr_val[idx];
            acc += v * g_support2[(size_t)src * NCLS + col];
        }
    }
    acc += __shfl_down_sync(0xffffffffu, acc, 16);
    float logit = acc + b2[col];
    float m = logit;
#pragma unroll
    for (int d = 8; d >= 1; d >>= 1) m = fmaxf(m, __shfl_xor_sync(0xffffffffu, m, d));
    float ev = __expf(logit - m);
    float sum = ev;
#pragma unroll
    for (int d = 8; d >= 1; d >>= 1) sum += __shfl_xor_sync(0xffffffffu, sum, d);
    if (lane < 16) out[(size_t)warp * NCLS + col] = ev / sum;
}

// ---------------- launch ----------------
extern "C" void kernel_launch(void* const* d_in, const int* in_sizes, int n_in,
                              void* d_out, int out_size) {
    const float* x        = (const float*)d_in[0];
    const int*   edge_src = (const int*)d_in[1];
    const int*   edge_dst = (const int*)d_in[2];
    const float* edge_val = (const float*)d_in[3];
    const float* W1       = (const float*)d_in[4];
    const float* b1       = (const float*)d_in[5];
    const float* W2       = (const float*)d_in[6];
    const float* b2       = (const float*)d_in[7];
    float* out = (float*)d_out;

    int E = in_sizes[1];
    int N = in_sizes[0] / FIN;

    int nblkN = (N + 255) / 256;
    int nblkE = (E + 255) / 256;
    int nbScan = (N + 511) / 512;

    // gemm1 (independent of CSR build) placed 4th: both prior profiled rounds
    // ncu captured the 4th launch, so this gets the dominant kernel profiled.
    zero_cnt_kernel<<<nblkN, 256>>>(N);                               // 1
    hist_kernel<<<nblkE, 256>>>(edge_dst, E);                         // 2
    scan1_kernel<<<nbScan, 512>>>(N);                                 // 3
    gemm1_mma_kernel<<<(N + 127) / 128, 256>>>(x, W1, N);             // 4 <- profiled
    scan2_kernel<<<1, 256>>>(nbScan);                                 // 5
    scan3_kernel<<<nblkN, 256>>>(N);                                  // 6
    scatter_kernel<<<nblkE, 256>>>(edge_src, edge_dst, edge_val, E);  // 7
    spmm1_kernel<<<(N + 7) / 8, 256>>>(b1, N);                        // 8
    gemm2_kernel<<<(N + 15) / 16, 256>>>(W2, N);                      // 9
    spmm2_softmax_kernel<<<(N + 7) / 8, 256>>>(b2, out, N);           // 10
}

// round 17
// speedup vs baseline: 2.1479x; 1.0509x over previous
#include <cuda_runtime.h>
#include <cuda_bf16.h>
#include <math.h>
#include <stdint.h>

// Problem constants (dataset-fixed)
#define MAXN 100000
#define MAXE 1600000
#define FIN  512
#define HID  64
#define NCLS 16

// ---------------- device scratch (no allocation allowed) ----------------
__device__ float g_support1[MAXN * HID];     // x @ W1
__device__ float g_h[MAXN * HID];            // relu(A @ support1 + b1)
__device__ float g_support2[MAXN * NCLS];    // h @ W2
__device__ int   g_cnt[MAXN];
__device__ int   g_incl[MAXN];
__device__ int   g_rowoff[MAXN + 1];
__device__ int   g_blockSums[512];
__device__ int   g_blockOff[512];
__device__ int   g_csr_src[MAXE];
__device__ float g_csr_val[MAXE];
__device__ __nv_bfloat16 g_W1hi[FIN * HID];  // pre-split W1 (hi)
__device__ __nv_bfloat16 g_W1lo[FIN * HID];  // pre-split W1 (lo)

// ---------------- small utilities ----------------
__device__ __forceinline__ int warp_incl_scan(int v) {
    int lane = threadIdx.x & 31;
#pragma unroll
    for (int d = 1; d < 32; d <<= 1) {
        int t = __shfl_up_sync(0xffffffffu, v, d);
        if (lane >= d) v += t;
    }
    return v;
}

__device__ __forceinline__ uint32_t smem_u32(const void* p) {
    return (uint32_t)__cvta_generic_to_shared(p);
}

__device__ __forceinline__ void ldsm_x4(uint32_t* d, uint32_t addr) {
    asm volatile("ldmatrix.sync.aligned.m8n8.x4.shared.b16 {%0,%1,%2,%3}, [%4];"
                 : "=r"(d[0]), "=r"(d[1]), "=r"(d[2]), "=r"(d[3]) : "r"(addr));
}
__device__ __forceinline__ void ldsm_x4_t(uint32_t* d, uint32_t addr) {
    asm volatile("ldmatrix.sync.aligned.m8n8.x4.trans.shared.b16 {%0,%1,%2,%3}, [%4];"
                 : "=r"(d[0]), "=r"(d[1]), "=r"(d[2]), "=r"(d[3]) : "r"(addr));
}
__device__ __forceinline__ void mma16816(float* c, const uint32_t* a, uint32_t b0, uint32_t b1) {
    asm volatile("mma.sync.aligned.m16n8k16.row.col.f32.bf16.bf16.f32 "
                 "{%0,%1,%2,%3}, {%4,%5,%6,%7}, {%8,%9}, {%0,%1,%2,%3};"
                 : "+f"(c[0]), "+f"(c[1]), "+f"(c[2]), "+f"(c[3])
                 : "r"(a[0]), "r"(a[1]), "r"(a[2]), "r"(a[3]), "r"(b0), "r"(b1));
}

__global__ void zero_cnt_kernel(int n) {
    int i = blockIdx.x * 256 + threadIdx.x;
    if (i < n) g_cnt[i] = 0;
}

// pre-split W1 into hi/lo bf16 (runs once per launch; 32768 elems)
__global__ void split_w1_kernel(const float* __restrict__ W1) {
    int i = blockIdx.x * 256 + threadIdx.x;
    if (i < FIN * HID) {
        float w = W1[i];
        __nv_bfloat16 h = __float2bfloat16(w);
        g_W1hi[i] = h;
        g_W1lo[i] = __float2bfloat16(w - __bfloat162float(h));
    }
}

__global__ void hist_kernel(const int* __restrict__ dst, int e) {
    int i = blockIdx.x * 256 + threadIdx.x;
    if (i < e) atomicAdd(&g_cnt[dst[i]], 1);
}

// per-512-block inclusive scan of g_cnt -> g_incl, block totals -> g_blockSums
__global__ void scan1_kernel(int n) {
    __shared__ int warpS[16];
    int tid = threadIdx.x;
    int gid = blockIdx.x * 512 + tid;
    int v = (gid < n) ? g_cnt[gid] : 0;
    int s = warp_incl_scan(v);
    int wid = tid >> 5, lane = tid & 31;
    if (lane == 31) warpS[wid] = s;
    __syncthreads();
    if (wid == 0) {
        int wv = (lane < 16) ? warpS[lane] : 0;
        int ws = warp_incl_scan(wv);
        if (lane < 16) warpS[lane] = ws;
    }
    __syncthreads();
    int off = (wid > 0) ? warpS[wid - 1] : 0;
    s += off;
    if (gid < n) g_incl[gid] = s;
    if (tid == 511) g_blockSums[blockIdx.x] = s;
}

// exclusive scan of block sums (nb <= 256) -> g_blockOff
__global__ void scan2_kernel(int nb) {
    __shared__ int warpS[8];
    int tid = threadIdx.x;
    int v = (tid < nb) ? g_blockSums[tid] : 0;
    int s = warp_incl_scan(v);
    int wid = tid >> 5, lane = tid & 31;
    if (lane == 31) warpS[wid] = s;
    __syncthreads();
    if (wid == 0) {
        int wv = (lane < 8) ? warpS[lane] : 0;
        int ws = warp_incl_scan(wv);
        if (lane < 8) warpS[lane] = ws;
    }
    __syncthreads();
    int off = (wid > 0) ? warpS[wid - 1] : 0;
    if (tid < nb) g_blockOff[tid] = s + off - v;  // exclusive
}

// row offsets: rowoff[0]=0 ; rowoff[i+1] = incl[i] + blockOff[i/512]
// Also resets g_cnt so the scatter pass can reuse it.
__global__ void scan3_kernel(int n) {
    int gid = blockIdx.x * 256 + threadIdx.x;
    if (gid == 0) g_rowoff[0] = 0;
    if (gid < n) {
        g_rowoff[gid + 1] = g_incl[gid] + g_blockOff[gid >> 9];
        g_cnt[gid] = 0;
    }
}

__global__ void scatter_kernel(const int* __restrict__ src,
                               const int* __restrict__ dst,
                               const float* __restrict__ val, int e) {
    int i = blockIdx.x * 256 + threadIdx.x;
    if (i < e) {
        int d = dst[i];
        int p = g_rowoff[d] + atomicAdd(&g_cnt[d], 1);
        g_csr_src[p] = src[i];
        g_csr_val[p] = val[i];
    }
}

// ---------------- GEMM1 (tensor cores): support1 = x[N,512] @ W1[512,64] ---
// bf16 hi/lo split, 3 HMMA products (hi*hi + hi*lo + lo*hi), fp32 accum.
// Software-pipelined: next chunk's A/B prefetched into registers during MMA.
// B comes pre-split from g_W1hi/g_W1lo (pure uint4 copies into smem).
#define APITCH 40   // bf16 elems per A smem row (80B: conflict-free ldmatrix)
#define BPITCH 72   // bf16 elems per B smem row (144B: conflict-free ldmatrix)

__global__ __launch_bounds__(256) void gemm1_mma_kernel(const float* __restrict__ x,
                                                        int N) {
    __shared__ __align__(16) __nv_bfloat16 Ahi[128 * APITCH];
    __shared__ __align__(16) __nv_bfloat16 Alo[128 * APITCH];
    __shared__ __align__(16) __nv_bfloat16 Bhi[32 * BPITCH];
    __shared__ __align__(16) __nv_bfloat16 Blo[32 * BPITCH];

    int tid = threadIdx.x, lane = tid & 31, warp = tid >> 5;
    int block_row = blockIdx.x * 128;

    float acc[8][4];
#pragma unroll
    for (int i = 0; i < 8; i++)
#pragma unroll
        for (int j = 0; j < 4; j++) acc[i][j] = 0.f;

    int a_f4 = tid & 7;   // float4 index within 32-wide k-chunk
    int a_r  = tid >> 3;  // 0..31 (rows r, r+32, r+64, r+96)
    int b_r  = tid >> 3;  // 0..31: B k-row
    int b_c8 = (tid & 7) * 8;  // B column group (8 bf16 = 16B)

    bool rv[4];
    const float* xrow[4];
#pragma unroll
    for (int i = 0; i < 4; i++) {
        int gr = block_row + a_r + 32 * i;
        rv[i] = gr < N;
        xrow[i] = x + (size_t)gr * FIN + a_f4 * 4;
    }
    const __nv_bfloat16* w1hi = g_W1hi + (size_t)b_r * HID + b_c8;
    const __nv_bfloat16* w1lo = g_W1lo + (size_t)b_r * HID + b_c8;

    int m0 = warp * 16;
    uint32_t aHiAddr = smem_u32(&Ahi[(m0 + (lane & 15)) * APITCH + (lane >> 4) * 8]);
    uint32_t aLoAddr = smem_u32(&Alo[(m0 + (lane & 15)) * APITCH + (lane >> 4) * 8]);
    uint32_t bHiAddr = smem_u32(&Bhi[(lane & 15) * BPITCH + (lane >> 4) * 8]);
    uint32_t bLoAddr = smem_u32(&Blo[(lane & 15) * BPITCH + (lane >> 4) * 8]);

    // register staging for the current chunk
    float4 aReg[4];
    uint4  bhReg, blReg;

    // prologue: load chunk 0
#pragma unroll
    for (int i = 0; i < 4; i++)
        aReg[i] = rv[i] ? *(const float4*)(xrow[i]) : make_float4(0.f, 0.f, 0.f, 0.f);
    bhReg = *(const uint4*)(w1hi);
    blReg = *(const uint4*)(w1lo);

    for (int k0 = 0; k0 < FIN; k0 += 32) {
        // ---- store staged A (split) + B (copy) into smem ----
#pragma unroll
        for (int i = 0; i < 4; i++) {
            int r = a_r + 32 * i;
            float vv[4] = {aReg[i].x, aReg[i].y, aReg[i].z, aReg[i].w};
            __nv_bfloat16 h[4], l[4];
#pragma unroll
            for (int j = 0; j < 4; j++) {
                h[j] = __float2bfloat16(vv[j]);
                l[j] = __float2bfloat16(vv[j] - __bfloat162float(h[j]));
            }
            int base = r * APITCH + a_f4 * 4;
            *(__nv_bfloat162*)&Ahi[base]     = __nv_bfloat162(h[0], h[1]);
            *(__nv_bfloat162*)&Ahi[base + 2] = __nv_bfloat162(h[2], h[3]);
            *(__nv_bfloat162*)&Alo[base]     = __nv_bfloat162(l[0], l[1]);
            *(__nv_bfloat162*)&Alo[base + 2] = __nv_bfloat162(l[2], l[3]);
        }
        *(uint4*)&Bhi[b_r * BPITCH + b_c8] = bhReg;
        *(uint4*)&Blo[b_r * BPITCH + b_c8] = blReg;
        __syncthreads();

        // ---- prefetch next chunk into registers (overlaps MMA below) ----
        int kn = k0 + 32;
        if (kn < FIN) {
#pragma unroll
            for (int i = 0; i < 4; i++)
                aReg[i] = rv[i] ? *(const float4*)(xrow[i] + kn) : make_float4(0.f, 0.f, 0.f, 0.f);
            bhReg = *(const uint4*)(w1hi + (size_t)kn * HID);
            blReg = *(const uint4*)(w1lo + (size_t)kn * HID);
        }

        // ---- MMA over the chunk in smem ----
#pragma unroll
        for (int k16 = 0; k16 < 2; k16++) {
            uint32_t ah[4], al[4];
            ldsm_x4(ah, aHiAddr + k16 * 32);          // 16 bf16 = 32B col offset
            ldsm_x4(al, aLoAddr + k16 * 32);
            uint32_t bh[4][4], bl[4][4];
#pragma unroll
            for (int p = 0; p < 4; p++) {
                uint32_t koff = (uint32_t)(k16 * 16 * BPITCH * 2);
                ldsm_x4_t(bh[p], bHiAddr + koff + p * 32);
                ldsm_x4_t(bl[p], bLoAddr + koff + p * 32);
            }
#pragma unroll
            for (int p = 0; p < 4; p++) {
#pragma unroll
                for (int hh = 0; hh < 2; hh++) {
                    int nb = p * 2 + hh;
                    mma16816(acc[nb], ah, bh[p][2 * hh], bh[p][2 * hh + 1]);
                    mma16816(acc[nb], ah, bl[p][2 * hh], bl[p][2 * hh + 1]);
                    mma16816(acc[nb], al, bh[p][2 * hh], bh[p][2 * hh + 1]);
                }
            }
        }
        __syncthreads();
    }

    // epilogue: c0,c1 -> row m0+(lane>>2), cols nb*8+(lane&3)*2; c2,c3 -> row+8
    int er = block_row + m0 + (lane >> 2);
    int ec = (lane & 3) * 2;
#pragma unroll
    for (int nb = 0; nb < 8; nb++) {
        if (er < N)
            *(float2*)&g_support1[(size_t)er * HID + nb * 8 + ec] =
                make_float2(acc[nb][0], acc[nb][1]);
        if (er + 8 < N)
            *(float2*)&g_support1[(size_t)(er + 8) * HID + nb * 8 + ec] =
                make_float2(acc[nb][2], acc[nb][3]);
    }
}

// ---------------- SpMM1: h = relu(A @ support1 + b1) ----------------
// Warp per node; half-warp per edge, float4 per lane; 2x unrolled (4 edges
// in flight) for higher gather MLP.
__global__ __launch_bounds__(256) void spmm1_kernel(const float* __restrict__ b1, int N) {
    int warp = (blockIdx.x * blockDim.x + threadIdx.x) >> 5;
    int lane = threadIdx.x & 31;
    if (warp >= N) return;
    int s = g_rowoff[warp];
    int e = g_rowoff[warp + 1];
    int half = lane >> 4;
    int c4 = (lane & 15) * 4;
    float4 acc  = make_float4(0.f, 0.f, 0.f, 0.f);
    float4 acc2 = make_float4(0.f, 0.f, 0.f, 0.f);
    int i = s;
    for (; i + 3 < e; i += 4) {
        int i0 = i + half;
        int i1 = i + 2 + half;
        int s0 = g_csr_src[i0];
        int s1 = g_csr_src[i1];
        float v0 = g_csr_val[i0];
        float v1 = g_csr_val[i1];
        float4 r0 = *(const float4*)&g_support1[(size_t)s0 * HID + c4];
        float4 r1 = *(const float4*)&g_support1[(size_t)s1 * HID + c4];
        acc.x  += v0 * r0.x; acc.y  += v0 * r0.y; acc.z  += v0 * r0.z; acc.w  += v0 * r0.w;
        acc2.x += v1 * r1.x; acc2.y += v1 * r1.y; acc2.z += v1 * r1.z; acc2.w += v1 * r1.w;
    }
    for (; i + half < e; i += 2) {
        int idx = i + half;
        int src = g_csr_src[idx];
        float v = g_csr_val[idx];
        float4 r = *(const float4*)&g_support1[(size_t)src * HID + c4];
        acc.x += v * r.x; acc.y += v * r.y; acc.z += v * r.z; acc.w += v * r.w;
    }
    acc.x += acc2.x; acc.y += acc2.y; acc.z += acc2.z; acc.w += acc2.w;
    acc.x += __shfl_down_sync(0xffffffffu, acc.x, 16);
    acc.y += __shfl_down_sync(0xffffffffu, acc.y, 16);
    acc.z += __shfl_down_sync(0xffffffffu, acc.z, 16);
    acc.w += __shfl_down_sync(0xffffffffu, acc.w, 16);
    if (lane < 16) {
        float4 bb = *(const float4*)&b1[c4];
        float4 o;
        o.x = fmaxf(acc.x + bb.x, 0.f);
        o.y = fmaxf(acc.y + bb.y, 0.f);
        o.z = fmaxf(acc.z + bb.z, 0.f);
        o.w = fmaxf(acc.w + bb.w, 0.f);
        *(float4*)&g_h[(size_t)warp * HID + c4] = o;
    }
}

// ---------------- GEMM2: support2 = h[N,64] @ W2[64,16] ----------------
__global__ __launch_bounds__(256) void gemm2_kernel(const float* __restrict__ W2, int N) {
    __shared__ float Ws[HID * NCLS];
    int tid = threadIdx.x;
    for (int i = tid; i < HID * NCLS; i += 256) Ws[i] = W2[i];
    __syncthreads();
    int lane = tid & 31, wid = tid >> 5;
    int row = (blockIdx.x * 8 + wid) * 2 + (lane >> 4);
    int col = lane & 15;
    if (row >= N) return;
    const float* hr = &g_h[(size_t)row * HID];
    float acc = 0.f;
#pragma unroll
    for (int k = 0; k < HID; k++) acc += hr[k] * Ws[k * NCLS + col];
    g_support2[(size_t)row * NCLS + col] = acc;
}

// ------- SpMM2 + b2 + softmax: out = softmax(A @ support2 + b2) ---------
__global__ __launch_bounds__(256) void spmm2_softmax_kernel(const float* __restrict__ b2,
                                                            float* __restrict__ out, int N) {
    int warp = (blockIdx.x * blockDim.x + threadIdx.x) >> 5;
    int lane = threadIdx.x & 31;
    if (warp >= N) return;
    int s = g_rowoff[warp];
    int e = g_rowoff[warp + 1];
    int col = lane & 15;
    float acc = 0.f;
    for (int i = s; i < e; i += 2) {
        int idx = i + (lane >> 4);
        if (idx < e) {
            int src = g_csr_src[idx];
            float v = g_csr_val[idx];
            acc += v * g_support2[(size_t)src * NCLS + col];
        }
    }
    acc += __shfl_down_sync(0xffffffffu, acc, 16);
    float logit = acc + b2[col];
    float m = logit;
#pragma unroll
    for (int d = 8; d >= 1; d >>= 1) m = fmaxf(m, __shfl_xor_sync(0xffffffffu, m, d));
    float ev = __expf(logit - m);
    float sum = ev;
#pragma unroll
    for (int d = 8; d >= 1; d >>= 1) sum += __shfl_xor_sync(0xffffffffu, sum, d);
    if (lane < 16) out[(size_t)warp * NCLS + col] = ev / sum;
}

// ---------------- launch ----------------
extern "C" void kernel_launch(void* const* d_in, const int* in_sizes, int n_in,
                              void* d_out, int out_size) {
    const float* x        = (const float*)d_in[0];
    const int*   edge_src = (const int*)d_in[1];
    const int*   edge_dst = (const int*)d_in[2];
    const float* edge_val = (const float*)d_in[3];
    const float* W1       = (const float*)d_in[4];
    const float* b1       = (const float*)d_in[5];
    const float* W2       = (const float*)d_in[6];
    const float* b2       = (const float*)d_in[7];
    float* out = (float*)d_out;

    int E = in_sizes[1];
    int N = in_sizes[0] / FIN;

    int nblkN = (N + 255) / 256;
    int nblkE = (E + 255) / 256;
    int nbScan = (N + 511) / 512;

    zero_cnt_kernel<<<nblkN, 256>>>(N);                               // 1
    hist_kernel<<<nblkE, 256>>>(edge_dst, E);                         // 2
    split_w1_kernel<<<(FIN * HID + 255) / 256, 256>>>(W1);            // 3
    gemm1_mma_kernel<<<(N + 127) / 128, 256>>>(x, N);                 // 4 <- profiled
    scan1_kernel<<<nbScan, 512>>>(N);                                 // 5
    scan2_kernel<<<1, 256>>>(nbScan);                                 // 6
    scan3_kernel<<<nblkN, 256>>>(N);                                  // 7
    scatter_kernel<<<nblkE, 256>>>(edge_src, edge_dst, edge_val, E);  // 8
    spmm1_kernel<<<(N + 7) / 8, 256>>>(b1, N);                        // 9
    gemm2_kernel<<<(N + 15) / 16, 256>>>(W2, N);                      // 10
    spmm2_softmax_kernel<<<(N + 7) / 8, 256>>>(b2, out, N);           // 11
}